// round 9
// baseline (speedup 1.0000x reference)
#include <cuda_runtime.h>
#include <cstdint>

// ===========================================================================
// Problem constants
// ===========================================================================
namespace {
constexpr int kB  = 2;
constexpr int kS  = 2048;
constexpr int kD  = 1024;
constexpr int kH  = 16;
constexpr int kDK = 64;
constexpr int kBH = kB * kH;        // 32
constexpr int kBS = kB * kS;        // 4096
constexpr int kNRows = kBH * kS;    // 65536

// proj smem tiles: [32 k][133 pad] uint32, 4 tiles (Ah, Al, Bh, Bl)
constexpr int kPTile  = 32 * 133;                  // uint32 elements per tile
constexpr int kPSmem  = 4 * kPTile * 4;            // 68096 bytes

// scores smem: Qs[64][132] + Kb[64][132] floats
constexpr int kSStride = 132;
constexpr int kSSmem   = 2 * 64 * kSStride * 4;    // 67584 bytes

// out smem: As[64][132] + Bs[64][68] floats
constexpr int kOAStride = 132;
constexpr int kOBStride = 68;
constexpr int kOSmem    = (64 * kOAStride + 64 * kOBStride) * 4;  // 51200 bytes
}

// Scratch (allocation-free rule: __device__ globals)
__device__ float g_q [kBH * kS * kDK];   // 16 MB
__device__ float g_kr[kBH * kS * kDK];   // 16 MB (k_proj + r_proj)
__device__ float g_v [kBH * kS * kDK];   // 16 MB
__device__ float g_rinv[kNRows];

// ===========================================================================
// tf32 helpers (arch-neutral PTX, valid on sm_100 target)
// ===========================================================================
__device__ __forceinline__ void split_tf32(float x, uint32_t& hi, uint32_t& lo) {
    uint32_t h;
    asm("cvt.rna.tf32.f32 %0, %1;" : "=r"(h) : "f"(x));
    float lf = x - __uint_as_float(h);
    uint32_t l;
    asm("cvt.rna.tf32.f32 %0, %1;" : "=r"(l) : "f"(lf));
    hi = h; lo = l;
}

// D += A(tf32) * B(tf32); m16n8k8, A row-major, B col-major.
__device__ __forceinline__ void mma_m16n8k8_tf32(float* d, const uint32_t* a,
                                                 const uint32_t* b) {
    asm volatile(
        "mma.sync.aligned.m16n8k8.row.col.f32.tf32.tf32.f32 "
        "{%0,%1,%2,%3}, {%4,%5,%6,%7}, {%8,%9}, {%0,%1,%2,%3};"
        : "+f"(d[0]), "+f"(d[1]), "+f"(d[2]), "+f"(d[3])
        : "r"(a[0]), "r"(a[1]), "r"(a[2]), "r"(a[3]), "r"(b[0]), "r"(b[1]));
}

// ===========================================================================
// Projection GEMM via mma.sync tf32x3, hi/lo split PRE-COMPUTED in smem.
// (measured ~790us total for 3 launches; unchanged from R8)
// ===========================================================================
__global__ __launch_bounds__(256) void proj_mma_kernel(
    const float* __restrict__ X1, const float* __restrict__ W1, const float* __restrict__ b1,
    const float* __restrict__ X2, const float* __restrict__ W2, const float* __restrict__ b2,
    int dst_sel, int ns)
{
    extern __shared__ uint32_t smem_u[];
    uint32_t* Ah = smem_u;
    uint32_t* Al = smem_u + kPTile;
    uint32_t* Bh = smem_u + 2 * kPTile;
    uint32_t* Bl = smem_u + 3 * kPTile;

    const int tid   = threadIdx.x;
    const int wid   = tid >> 5;
    const int lane  = tid & 31;
    const int gid   = lane >> 2;          // 0..7
    const int tid4  = lane & 3;           // 0..3
    const int wm    = (wid >> 2) * 64;    // warp m-offset: 0 / 64
    const int wn    = (wid & 3) * 32;     // warp n-offset: 0/32/64/96
    const int m0    = blockIdx.y * 128;
    const int n0    = blockIdx.x * 128;

    float acc[4][4][4];
#pragma unroll
    for (int mt = 0; mt < 4; ++mt)
#pragma unroll
        for (int nt = 0; nt < 4; ++nt)
#pragma unroll
            for (int f = 0; f < 4; ++f) acc[mt][nt][f] = 0.f;

    for (int s = 0; s < ns; ++s) {
        const float* __restrict__ X = (s < 32) ? X1 : X2;
        const float* __restrict__ W = (s < 32) ? W1 : W2;
        const int k0 = (s & 31) * 32;

        float4 xa[4], wb[4];
#pragma unroll
        for (int i = 0; i < 4; ++i) {
            const int idx = tid + 256 * i;
            const int row = idx >> 3;
            const int c4  = (idx & 7) * 4;
            xa[i] = *reinterpret_cast<const float4*>(&X[(size_t)(m0 + row) * kD + k0 + c4]);
            wb[i] = *reinterpret_cast<const float4*>(&W[(size_t)(n0 + row) * kD + k0 + c4]);
        }
        __syncthreads();
#pragma unroll
        for (int i = 0; i < 4; ++i) {
            const int idx = tid + 256 * i;
            const int row = idx >> 3;
            const int c4  = (idx & 7) * 4;
            const float* xv = reinterpret_cast<const float*>(&xa[i]);
            const float* wv = reinterpret_cast<const float*>(&wb[i]);
#pragma unroll
            for (int j = 0; j < 4; ++j) {
                uint32_t h, l;
                split_tf32(xv[j], h, l);
                Ah[(c4 + j) * 133 + row] = h;
                Al[(c4 + j) * 133 + row] = l;
                split_tf32(wv[j], h, l);
                Bh[(c4 + j) * 133 + row] = h;
                Bl[(c4 + j) * 133 + row] = l;
            }
        }
        __syncthreads();

#pragma unroll
        for (int kk = 0; kk < 4; ++kk) {
            const int kb = kk * 8;

            uint32_t bhf[4][2], blf[4][2];
#pragma unroll
            for (int nt = 0; nt < 4; ++nt) {
                const int n = wn + nt * 8 + gid;
                bhf[nt][0] = Bh[(kb + tid4) * 133 + n];
                bhf[nt][1] = Bh[(kb + tid4 + 4) * 133 + n];
                blf[nt][0] = Bl[(kb + tid4) * 133 + n];
                blf[nt][1] = Bl[(kb + tid4 + 4) * 133 + n];
            }

#pragma unroll
            for (int mt = 0; mt < 4; ++mt) {
                const int m = wm + mt * 16 + gid;
                uint32_t ah[4], al[4];
                ah[0] = Ah[(kb + tid4) * 133 + m];
                ah[1] = Ah[(kb + tid4) * 133 + m + 8];
                ah[2] = Ah[(kb + tid4 + 4) * 133 + m];
                ah[3] = Ah[(kb + tid4 + 4) * 133 + m + 8];
                al[0] = Al[(kb + tid4) * 133 + m];
                al[1] = Al[(kb + tid4) * 133 + m + 8];
                al[2] = Al[(kb + tid4 + 4) * 133 + m];
                al[3] = Al[(kb + tid4 + 4) * 133 + m + 8];
#pragma unroll
                for (int nt = 0; nt < 4; ++nt) {
                    mma_m16n8k8_tf32(acc[mt][nt], ah, bhf[nt]);
                    mma_m16n8k8_tf32(acc[mt][nt], ah, blf[nt]);
                    mma_m16n8k8_tf32(acc[mt][nt], al, bhf[nt]);
                }
            }
        }
    }

    float* __restrict__ dst = (dst_sel == 0) ? g_q : (dst_sel == 1) ? g_kr : g_v;
#pragma unroll
    for (int nt = 0; nt < 4; ++nt) {
        const int e  = n0 + wn + nt * 8 + 2 * tid4;
        const int h  = e >> 6;
        const int dk = e & 63;
        float2 bb;
        bb.x = b1[e];     bb.y = b1[e + 1];
        if (X2) { bb.x += b2[e]; bb.y += b2[e + 1]; }
#pragma unroll
        for (int mt = 0; mt < 4; ++mt) {
#pragma unroll
            for (int half = 0; half < 2; ++half) {
                const int gm   = m0 + wm + mt * 16 + gid + half * 8;
                const int bidx = gm >> 11;
                const int srow = gm & (kS - 1);
                float2 o;
                o.x = acc[mt][nt][half * 2 + 0] + bb.x;
                o.y = acc[mt][nt][half * 2 + 1] + bb.y;
                *reinterpret_cast<float2*>(
                    &dst[(((size_t)bidx * kH + h) * kS + srow) * kDK + dk]) = o;
            }
        }
    }
}

// ===========================================================================
// Fused scores + softmax numerator + row sums (max-free softmax).
// R9: full 128x64 KR chunk resident in smem -> sync-free 128x128x64 inner
// GEMM (2 syncs per n0 chunk instead of 16).
// grid (S/128, BH), 256 threads, dynamic smem kSSmem, 2 CTAs/SM.
// ===========================================================================
__global__ __launch_bounds__(256, 2) void scores_sum_kernel(const int* __restrict__ mask,
                                                            float* __restrict__ p)
{
    extern __shared__ float sm_f[];
    float* Qs = sm_f;                       // [64][132]  [k][m]
    float* Kb = sm_f + 64 * kSStride;       // [64][132]  [k][n]

    const int bh  = blockIdx.y;
    const int m0  = blockIdx.x * 128;
    const int tid = threadIdx.x;
    const int tx  = tid & 15;
    const int ty  = tid >> 4;

    const float* __restrict__ Q  = g_q  + (size_t)bh * kS * kDK;
    const float* __restrict__ KR = g_kr + (size_t)bh * kS * kDK;

    // Load Q strip: rows m0..m0+127, all 64 k values, stored k-major.
    for (int i = tid; i < 128 * 16; i += 256) {
        const int row = i >> 4;
        const int kq  = (i & 15) * 4;
        float4 v = *reinterpret_cast<const float4*>(&Q[(size_t)(m0 + row) * kDK + kq]);
        Qs[(kq + 0) * kSStride + row] = v.x; Qs[(kq + 1) * kSStride + row] = v.y;
        Qs[(kq + 2) * kSStride + row] = v.z; Qs[(kq + 3) * kSStride + row] = v.w;
    }

    float rowsum[8];
#pragma unroll
    for (int i = 0; i < 8; ++i) rowsum[i] = 0.f;

    const int   b_    = bh >> 4;
    const float scale = 0.125f;

    for (int n0 = 0; n0 < kS; n0 += 128) {
        __syncthreads();   // protect Kb from previous iteration's compute
        for (int i = tid; i < 128 * 16; i += 256) {
            const int row = i >> 4;
            const int kq  = (i & 15) * 4;
            float4 v = *reinterpret_cast<const float4*>(&KR[(size_t)(n0 + row) * kDK + kq]);
            Kb[(kq + 0) * kSStride + row] = v.x; Kb[(kq + 1) * kSStride + row] = v.y;
            Kb[(kq + 2) * kSStride + row] = v.z; Kb[(kq + 3) * kSStride + row] = v.w;
        }
        __syncthreads();

        float acc[8][8];
#pragma unroll
        for (int i = 0; i < 8; ++i)
#pragma unroll
            for (int j = 0; j < 8; ++j) acc[i][j] = 0.f;

        // sync-free inner GEMM: 128x128x64
#pragma unroll 8
        for (int kk = 0; kk < 64; ++kk) {
            float4 a0 = *reinterpret_cast<const float4*>(&Qs[kk * kSStride + ty * 8]);
            float4 a1 = *reinterpret_cast<const float4*>(&Qs[kk * kSStride + ty * 8 + 4]);
            float4 b0 = *reinterpret_cast<const float4*>(&Kb[kk * kSStride + tx * 8]);
            float4 b1 = *reinterpret_cast<const float4*>(&Kb[kk * kSStride + tx * 8 + 4]);
            float a[8] = {a0.x, a0.y, a0.z, a0.w, a1.x, a1.y, a1.z, a1.w};
            float b[8] = {b0.x, b0.y, b0.z, b0.w, b1.x, b1.y, b1.z, b1.w};
#pragma unroll
            for (int i = 0; i < 8; ++i)
#pragma unroll
                for (int j = 0; j < 8; ++j) acc[i][j] += a[i] * b[j];
        }

        // epilogue: mask -> exp -> store numerators -> accumulate row sums
#pragma unroll
        for (int i = 0; i < 8; ++i) {
            const int sq = m0 + ty * 8 + i;
            const int* __restrict__ mrow = &mask[((size_t)b_ * kS + sq) * kS];
            float* __restrict__ prow = &p[((size_t)bh * kS + sq) * kS];
#pragma unroll
            for (int j4 = 0; j4 < 8; j4 += 4) {
                const int sk = n0 + tx * 8 + j4;
                int4 mm = *reinterpret_cast<const int4*>(&mrow[sk]);
                float4 e;
                e.x = mm.x ? __expf(acc[i][j4 + 0] * scale) : 0.f;
                e.y = mm.y ? __expf(acc[i][j4 + 1] * scale) : 0.f;
                e.z = mm.z ? __expf(acc[i][j4 + 2] * scale) : 0.f;
                e.w = mm.w ? __expf(acc[i][j4 + 3] * scale) : 0.f;
                *reinterpret_cast<float4*>(&prow[sk]) = e;
                rowsum[i] += (e.x + e.y) + (e.z + e.w);
            }
        }
    }

#pragma unroll
    for (int i = 0; i < 8; ++i) {
        float s = rowsum[i];
        s += __shfl_xor_sync(0xffffffffu, s, 1);
        s += __shfl_xor_sync(0xffffffffu, s, 2);
        s += __shfl_xor_sync(0xffffffffu, s, 4);
        s += __shfl_xor_sync(0xffffffffu, s, 8);
        if (tx == 0) g_rinv[bh * kS + m0 + ty * 8 + i] = 1.0f / s;
    }
}

// ===========================================================================
// out = p @ v with on-the-fly normalization; writes final p back.
// R9: BK=64 (was 16) -> 64 sync-free k-steps per stage, 4x fewer syncs.
// grid (S/128, BH), 256 threads, dynamic smem kOSmem, 2 CTAs/SM.
// ===========================================================================
__global__ __launch_bounds__(256, 2) void out_kernel(float* __restrict__ p,
                                                     float* __restrict__ out)
{
    extern __shared__ float sm_f[];
    float* As = sm_f;                        // [64][132]  [k][m], normalized p
    float* Bs = sm_f + 64 * kOAStride;       // [64][68]   [k][n], V
    __shared__ float s_inv[128];

    const int bh  = blockIdx.y;
    const int m0  = blockIdx.x * 128;
    const int tid = threadIdx.x;
    const int tx  = tid & 15;
    const int ty  = tid >> 4;

    if (tid < 128) {
        s_inv[tid] = g_rinv[bh * kS + m0 + tid];
    }
    __syncthreads();

    float acc[8][4];
#pragma unroll
    for (int i = 0; i < 8; ++i)
#pragma unroll
        for (int j = 0; j < 4; ++j) acc[i][j] = 0.f;

    float* __restrict__ prow = p + (size_t)bh * kS * kS + (size_t)m0 * kS;
    const float* __restrict__ V = g_v + (size_t)bh * kS * kDK;

    for (int k0 = 0; k0 < kS; k0 += 64) {
        __syncthreads();   // protect As/Bs from previous compute
        // p tile: 128 m-rows x 64 k; normalize, stash [k][m], write back
        for (int i = tid; i < 128 * 16; i += 256) {
            const int row = i >> 4;
            const int kq  = (i & 15) * 4;
            const float iv = s_inv[row];
            float4 x = *reinterpret_cast<const float4*>(&prow[(size_t)row * kS + k0 + kq]);
            x.x *= iv; x.y *= iv; x.z *= iv; x.w *= iv;
            As[(kq + 0) * kOAStride + row] = x.x;
            As[(kq + 1) * kOAStride + row] = x.y;
            As[(kq + 2) * kOAStride + row] = x.z;
            As[(kq + 3) * kOAStride + row] = x.w;
            *reinterpret_cast<float4*>(&prow[(size_t)row * kS + k0 + kq]) = x;
        }
        // V tile: 64 k-rows x 64 n
        for (int i = tid; i < 64 * 16; i += 256) {
            const int vk = i >> 4;
            const int vn = (i & 15) * 4;
            float4 vb = *reinterpret_cast<const float4*>(&V[(size_t)(k0 + vk) * kDK + vn]);
            *reinterpret_cast<float4*>(&Bs[vk * kOBStride + vn]) = vb;
        }
        __syncthreads();

#pragma unroll 8
        for (int kk = 0; kk < 64; ++kk) {
            float4 a0 = *reinterpret_cast<const float4*>(&As[kk * kOAStride + ty * 8]);
            float4 a1 = *reinterpret_cast<const float4*>(&As[kk * kOAStride + ty * 8 + 4]);
            float4 bb = *reinterpret_cast<const float4*>(&Bs[kk * kOBStride + tx * 4]);
            float a[8]  = {a0.x, a0.y, a0.z, a0.w, a1.x, a1.y, a1.z, a1.w};
            float bj[4] = {bb.x, bb.y, bb.z, bb.w};
#pragma unroll
            for (int i = 0; i < 8; ++i)
#pragma unroll
                for (int j = 0; j < 4; ++j) acc[i][j] += a[i] * bj[j];
        }
    }

    float* __restrict__ orow = out + (size_t)bh * kS * kDK;
#pragma unroll
    for (int i = 0; i < 8; ++i) {
        float4 o = make_float4(acc[i][0], acc[i][1], acc[i][2], acc[i][3]);
        *reinterpret_cast<float4*>(&orow[(m0 + ty * 8 + i) * kDK + tx * 4]) = o;
    }
}

// ===========================================================================
extern "C" void kernel_launch(void* const* d_in, const int* in_sizes, int n_in,
                              void* d_out, int out_size)
{
    (void)in_sizes; (void)n_in; (void)out_size;
    const float* query = (const float*)d_in[0];
    const float* key   = (const float*)d_in[1];
    const float* value = (const float*)d_in[2];
    const float* r     = (const float*)d_in[3];
    const int*   mask  = (const int*)  d_in[4];
    const float* Wq = (const float*)d_in[5];  const float* bq = (const float*)d_in[6];
    const float* Wk = (const float*)d_in[7];  const float* bk = (const float*)d_in[8];
    const float* Wv = (const float*)d_in[9];  const float* bv = (const float*)d_in[10];
    const float* Wr = (const float*)d_in[11]; const float* br = (const float*)d_in[12];

    float* out = (float*)d_out;                          // (B,H,S,DK)
    float* p   = out + (size_t)kBH * kS * kDK;           // (B,H,S,S)

    cudaFuncSetAttribute(proj_mma_kernel,
                         cudaFuncAttributeMaxDynamicSharedMemorySize, kPSmem);
    cudaFuncSetAttribute(scores_sum_kernel,
                         cudaFuncAttributeMaxDynamicSharedMemorySize, kSSmem);
    cudaFuncSetAttribute(out_kernel,
                         cudaFuncAttributeMaxDynamicSharedMemorySize, kOSmem);

    dim3 pgrid(kD / 128, kBS / 128);                     // (8, 32)
    proj_mma_kernel<<<pgrid, 256, kPSmem>>>(query, Wq, bq, nullptr, nullptr, nullptr, 0, 32);
    proj_mma_kernel<<<pgrid, 256, kPSmem>>>(key,   Wk, bk, r, Wr, br, 1, 64);  // kr
    proj_mma_kernel<<<pgrid, 256, kPSmem>>>(value, Wv, bv, nullptr, nullptr, nullptr, 2, 32);

    dim3 sgrid(kS / 128, kBH);                           // (16, 32)
    scores_sum_kernel<<<sgrid, 256, kSSmem>>>(mask, p);

    dim3 ogrid(kS / 128, kBH);                           // (16, 32)
    out_kernel<<<ogrid, 256, kOSmem>>>(p, out);
}

// round 10
// speedup vs baseline: 1.0887x; 1.0887x over previous
#include <cuda_runtime.h>
#include <cstdint>

// ===========================================================================
// Problem constants
// ===========================================================================
namespace {
constexpr int kB  = 2;
constexpr int kS  = 2048;
constexpr int kD  = 1024;
constexpr int kH  = 16;
constexpr int kDK = 64;
constexpr int kBH = kB * kH;        // 32
constexpr int kBS = kB * kS;        // 4096
constexpr int kNRows = kBH * kS;    // 65536

// proj smem tiles: [32 k][133 pad] uint32, 4 tiles (Ah, Al, Bh, Bl)
constexpr int kPTile  = 32 * 133;                  // uint32 elements per tile
constexpr int kPSmem  = 4 * kPTile * 4;            // 68096 bytes
}

// Scratch (allocation-free rule: __device__ globals)
__device__ float g_q [kBH * kS * kDK];   // 16 MB
__device__ float g_kr[kBH * kS * kDK];   // 16 MB (k_proj + r_proj)
__device__ float g_v [kBH * kS * kDK];   // 16 MB
__device__ float g_rinv[kNRows];

// ===========================================================================
// tf32 / f32x2 helpers (arch-neutral PTX, valid on sm_100 target)
// ===========================================================================
__device__ __forceinline__ void split_tf32(float x, uint32_t& hi, uint32_t& lo) {
    uint32_t h;
    asm("cvt.rna.tf32.f32 %0, %1;" : "=r"(h) : "f"(x));
    float lf = x - __uint_as_float(h);
    uint32_t l;
    asm("cvt.rna.tf32.f32 %0, %1;" : "=r"(l) : "f"(lf));
    hi = h; lo = l;
}

// D += A(tf32) * B(tf32); m16n8k8, A row-major, B col-major.
__device__ __forceinline__ void mma_m16n8k8_tf32(float* d, const uint32_t* a,
                                                 const uint32_t* b) {
    asm volatile(
        "mma.sync.aligned.m16n8k8.row.col.f32.tf32.tf32.f32 "
        "{%0,%1,%2,%3}, {%4,%5,%6,%7}, {%8,%9}, {%0,%1,%2,%3};"
        : "+f"(d[0]), "+f"(d[1]), "+f"(d[2]), "+f"(d[3])
        : "r"(a[0]), "r"(a[1]), "r"(a[2]), "r"(a[3]), "r"(b[0]), "r"(b[1]));
}

// packed fp32x2 FMA: d = a * b + d  (per 32-bit lane)
__device__ __forceinline__ void fma_x2(unsigned long long& d,
                                       unsigned long long a, unsigned long long b) {
    asm("fma.rn.f32x2 %0, %1, %2, %0;" : "+l"(d) : "l"(a), "l"(b));
}
__device__ __forceinline__ unsigned long long pack_dup(float x) {
    unsigned long long r;
    asm("mov.b64 %0, {%1, %1};" : "=l"(r) : "f"(x));
    return r;
}
__device__ __forceinline__ void unpack_x2(unsigned long long v, float& lo, float& hi) {
    asm("mov.b64 {%0, %1}, %2;" : "=f"(lo), "=f"(hi) : "l"(v));
}

// ===========================================================================
// Projection GEMM via mma.sync tf32x3, hi/lo split PRE-COMPUTED in smem.
// (measured ~790us total for 3 launches; unchanged from R8)
// ===========================================================================
__global__ __launch_bounds__(256) void proj_mma_kernel(
    const float* __restrict__ X1, const float* __restrict__ W1, const float* __restrict__ b1,
    const float* __restrict__ X2, const float* __restrict__ W2, const float* __restrict__ b2,
    int dst_sel, int ns)
{
    extern __shared__ uint32_t smem_u[];
    uint32_t* Ah = smem_u;
    uint32_t* Al = smem_u + kPTile;
    uint32_t* Bh = smem_u + 2 * kPTile;
    uint32_t* Bl = smem_u + 3 * kPTile;

    const int tid   = threadIdx.x;
    const int wid   = tid >> 5;
    const int lane  = tid & 31;
    const int gid   = lane >> 2;          // 0..7
    const int tid4  = lane & 3;           // 0..3
    const int wm    = (wid >> 2) * 64;    // warp m-offset: 0 / 64
    const int wn    = (wid & 3) * 32;     // warp n-offset: 0/32/64/96
    const int m0    = blockIdx.y * 128;
    const int n0    = blockIdx.x * 128;

    float acc[4][4][4];
#pragma unroll
    for (int mt = 0; mt < 4; ++mt)
#pragma unroll
        for (int nt = 0; nt < 4; ++nt)
#pragma unroll
            for (int f = 0; f < 4; ++f) acc[mt][nt][f] = 0.f;

    for (int s = 0; s < ns; ++s) {
        const float* __restrict__ X = (s < 32) ? X1 : X2;
        const float* __restrict__ W = (s < 32) ? W1 : W2;
        const int k0 = (s & 31) * 32;

        float4 xa[4], wb[4];
#pragma unroll
        for (int i = 0; i < 4; ++i) {
            const int idx = tid + 256 * i;
            const int row = idx >> 3;
            const int c4  = (idx & 7) * 4;
            xa[i] = *reinterpret_cast<const float4*>(&X[(size_t)(m0 + row) * kD + k0 + c4]);
            wb[i] = *reinterpret_cast<const float4*>(&W[(size_t)(n0 + row) * kD + k0 + c4]);
        }
        __syncthreads();
#pragma unroll
        for (int i = 0; i < 4; ++i) {
            const int idx = tid + 256 * i;
            const int row = idx >> 3;
            const int c4  = (idx & 7) * 4;
            const float* xv = reinterpret_cast<const float*>(&xa[i]);
            const float* wv = reinterpret_cast<const float*>(&wb[i]);
#pragma unroll
            for (int j = 0; j < 4; ++j) {
                uint32_t h, l;
                split_tf32(xv[j], h, l);
                Ah[(c4 + j) * 133 + row] = h;
                Al[(c4 + j) * 133 + row] = l;
                split_tf32(wv[j], h, l);
                Bh[(c4 + j) * 133 + row] = h;
                Bl[(c4 + j) * 133 + row] = l;
            }
        }
        __syncthreads();

#pragma unroll
        for (int kk = 0; kk < 4; ++kk) {
            const int kb = kk * 8;

            uint32_t bhf[4][2], blf[4][2];
#pragma unroll
            for (int nt = 0; nt < 4; ++nt) {
                const int n = wn + nt * 8 + gid;
                bhf[nt][0] = Bh[(kb + tid4) * 133 + n];
                bhf[nt][1] = Bh[(kb + tid4 + 4) * 133 + n];
                blf[nt][0] = Bl[(kb + tid4) * 133 + n];
                blf[nt][1] = Bl[(kb + tid4 + 4) * 133 + n];
            }

#pragma unroll
            for (int mt = 0; mt < 4; ++mt) {
                const int m = wm + mt * 16 + gid;
                uint32_t ah[4], al[4];
                ah[0] = Ah[(kb + tid4) * 133 + m];
                ah[1] = Ah[(kb + tid4) * 133 + m + 8];
                ah[2] = Ah[(kb + tid4 + 4) * 133 + m];
                ah[3] = Ah[(kb + tid4 + 4) * 133 + m + 8];
                al[0] = Al[(kb + tid4) * 133 + m];
                al[1] = Al[(kb + tid4) * 133 + m + 8];
                al[2] = Al[(kb + tid4 + 4) * 133 + m];
                al[3] = Al[(kb + tid4 + 4) * 133 + m + 8];
#pragma unroll
                for (int nt = 0; nt < 4; ++nt) {
                    mma_m16n8k8_tf32(acc[mt][nt], ah, bhf[nt]);
                    mma_m16n8k8_tf32(acc[mt][nt], ah, blf[nt]);
                    mma_m16n8k8_tf32(acc[mt][nt], al, bhf[nt]);
                }
            }
        }
    }

    float* __restrict__ dst = (dst_sel == 0) ? g_q : (dst_sel == 1) ? g_kr : g_v;
#pragma unroll
    for (int nt = 0; nt < 4; ++nt) {
        const int e  = n0 + wn + nt * 8 + 2 * tid4;
        const int h  = e >> 6;
        const int dk = e & 63;
        float2 bb;
        bb.x = b1[e];     bb.y = b1[e + 1];
        if (X2) { bb.x += b2[e]; bb.y += b2[e + 1]; }
#pragma unroll
        for (int mt = 0; mt < 4; ++mt) {
#pragma unroll
            for (int half = 0; half < 2; ++half) {
                const int gm   = m0 + wm + mt * 16 + gid + half * 8;
                const int bidx = gm >> 11;
                const int srow = gm & (kS - 1);
                float2 o;
                o.x = acc[mt][nt][half * 2 + 0] + bb.x;
                o.y = acc[mt][nt][half * 2 + 1] + bb.y;
                *reinterpret_cast<float2*>(
                    &dst[(((size_t)bidx * kH + h) * kS + srow) * kDK + dk]) = o;
            }
        }
    }
}

// ===========================================================================
// Fused scores + softmax numerator + row sums (max-free softmax).
// R8 structure (measured 606us) + packed f32x2 FMA inner loop.
// ===========================================================================
__global__ __launch_bounds__(256, 2) void scores_sum_kernel(const int* __restrict__ mask,
                                                            float* __restrict__ p)
{
    __shared__ float Qs[64][132];
    __shared__ float Bs[8][128];

    const int bh  = blockIdx.y;
    const int m0  = blockIdx.x * 128;
    const int tid = threadIdx.x;
    const int tx  = tid & 15;
    const int ty  = tid >> 4;
    const int lr  = tid >> 1;
    const int lc  = (tid & 1) * 4;

    const float* __restrict__ Q  = g_q  + (size_t)bh * kS * kDK;
    const float* __restrict__ KR = g_kr + (size_t)bh * kS * kDK;

    for (int i = tid; i < 128 * 16; i += 256) {
        const int row = i >> 4;
        const int kq  = (i & 15) * 4;
        float4 v = *reinterpret_cast<const float4*>(&Q[(m0 + row) * kDK + kq]);
        Qs[kq + 0][row] = v.x; Qs[kq + 1][row] = v.y;
        Qs[kq + 2][row] = v.z; Qs[kq + 3][row] = v.w;
    }

    float rowsum[8];
#pragma unroll
    for (int i = 0; i < 8; ++i) rowsum[i] = 0.f;

    const int   b_    = bh >> 4;
    const float scale = 0.125f;

    for (int n0 = 0; n0 < kS; n0 += 128) {
        unsigned long long acc2[8][4];   // packed f32x2 accumulators (64 regs)
#pragma unroll
        for (int i = 0; i < 8; ++i)
#pragma unroll
            for (int j = 0; j < 4; ++j) acc2[i][j] = 0ull;

        for (int k0 = 0; k0 < kDK; k0 += 8) {
            float4 bv = *reinterpret_cast<const float4*>(&KR[(n0 + lr) * kDK + k0 + lc]);
            __syncthreads();
            Bs[lc + 0][lr] = bv.x; Bs[lc + 1][lr] = bv.y;
            Bs[lc + 2][lr] = bv.z; Bs[lc + 3][lr] = bv.w;
            __syncthreads();
#pragma unroll
            for (int kk = 0; kk < 8; ++kk) {
                float4 a0 = *reinterpret_cast<const float4*>(&Qs[k0 + kk][ty * 8]);
                float4 a1 = *reinterpret_cast<const float4*>(&Qs[k0 + kk][ty * 8 + 4]);
                ulonglong2 u0 = *reinterpret_cast<const ulonglong2*>(&Bs[kk][tx * 8]);
                ulonglong2 u1 = *reinterpret_cast<const ulonglong2*>(&Bs[kk][tx * 8 + 4]);
                unsigned long long bp[4] = {u0.x, u0.y, u1.x, u1.y};
                unsigned long long ad[8];
                ad[0] = pack_dup(a0.x); ad[1] = pack_dup(a0.y);
                ad[2] = pack_dup(a0.z); ad[3] = pack_dup(a0.w);
                ad[4] = pack_dup(a1.x); ad[5] = pack_dup(a1.y);
                ad[6] = pack_dup(a1.z); ad[7] = pack_dup(a1.w);
#pragma unroll
                for (int i = 0; i < 8; ++i)
#pragma unroll
                    for (int j = 0; j < 4; ++j)
                        fma_x2(acc2[i][j], ad[i], bp[j]);
            }
        }

        // epilogue: unpack -> mask -> exp -> store numerators -> row sums
#pragma unroll
        for (int i = 0; i < 8; ++i) {
            const int sq = m0 + ty * 8 + i;
            const int* __restrict__ mrow = &mask[((size_t)b_ * kS + sq) * kS];
            float* __restrict__ prow = &p[((size_t)bh * kS + sq) * kS];
#pragma unroll
            for (int j2 = 0; j2 < 2; ++j2) {
                const int sk = n0 + tx * 8 + j2 * 4;
                int4 mm = *reinterpret_cast<const int4*>(&mrow[sk]);
                float f0, f1, f2, f3;
                unpack_x2(acc2[i][j2 * 2 + 0], f0, f1);
                unpack_x2(acc2[i][j2 * 2 + 1], f2, f3);
                float4 e;
                e.x = mm.x ? __expf(f0 * scale) : 0.f;
                e.y = mm.y ? __expf(f1 * scale) : 0.f;
                e.z = mm.z ? __expf(f2 * scale) : 0.f;
                e.w = mm.w ? __expf(f3 * scale) : 0.f;
                *reinterpret_cast<float4*>(&prow[sk]) = e;
                rowsum[i] += (e.x + e.y) + (e.z + e.w);
            }
        }
    }

#pragma unroll
    for (int i = 0; i < 8; ++i) {
        float s = rowsum[i];
        s += __shfl_xor_sync(0xffffffffu, s, 1);
        s += __shfl_xor_sync(0xffffffffu, s, 2);
        s += __shfl_xor_sync(0xffffffffu, s, 4);
        s += __shfl_xor_sync(0xffffffffu, s, 8);
        if (tx == 0) g_rinv[bh * kS + m0 + ty * 8 + i] = 1.0f / s;
    }
}

// ===========================================================================
// out = p @ v with on-the-fly normalization; writes final p back.
// R8 structure (measured 450us) + packed f32x2 FMA inner loop.
// ===========================================================================
__global__ __launch_bounds__(256, 2) void out_kernel(float* __restrict__ p,
                                                     float* __restrict__ out)
{
    __shared__ float As[16][128];
    __shared__ float Bs[16][64];
    __shared__ float s_inv[128];

    const int bh  = blockIdx.y;
    const int m0  = blockIdx.x * 128;
    const int tid = threadIdx.x;
    const int tx  = tid & 15;
    const int ty  = tid >> 4;

    if (tid < 128) {
        s_inv[tid] = g_rinv[bh * kS + m0 + tid];
    }
    __syncthreads();

    unsigned long long acc2[8][2];     // packed f32x2 accumulators (32 regs)
#pragma unroll
    for (int i = 0; i < 8; ++i) { acc2[i][0] = 0ull; acc2[i][1] = 0ull; }

    float* __restrict__ prow = p + (size_t)bh * kS * kS + (size_t)m0 * kS;
    const float* __restrict__ V = g_v + (size_t)bh * kS * kDK;

    const int r0 = tid >> 2;
    const int c0 = (tid & 3) * 4;
    const int vk = tid >> 4;
    const int vn = (tid & 15) * 4;

    const float iv0 = s_inv[r0];
    const float iv1 = s_inv[r0 + 64];

    for (int k0 = 0; k0 < kS; k0 += 16) {
        float4 x0 = *reinterpret_cast<const float4*>(&prow[(size_t)r0 * kS + k0 + c0]);
        float4 x1 = *reinterpret_cast<const float4*>(&prow[(size_t)(r0 + 64) * kS + k0 + c0]);
        float4 n0v, n1v;
        n0v.x = x0.x * iv0;  n0v.y = x0.y * iv0;
        n0v.z = x0.z * iv0;  n0v.w = x0.w * iv0;
        n1v.x = x1.x * iv1;  n1v.y = x1.y * iv1;
        n1v.z = x1.z * iv1;  n1v.w = x1.w * iv1;

        float4 vb = *reinterpret_cast<const float4*>(&V[(k0 + vk) * kDK + vn]);

        __syncthreads();
        As[c0 + 0][r0]      = n0v.x; As[c0 + 1][r0]      = n0v.y;
        As[c0 + 2][r0]      = n0v.z; As[c0 + 3][r0]      = n0v.w;
        As[c0 + 0][r0 + 64] = n1v.x; As[c0 + 1][r0 + 64] = n1v.y;
        As[c0 + 2][r0 + 64] = n1v.z; As[c0 + 3][r0 + 64] = n1v.w;
        *reinterpret_cast<float4*>(&Bs[vk][vn]) = vb;

        *reinterpret_cast<float4*>(&prow[(size_t)r0 * kS + k0 + c0])        = n0v;
        *reinterpret_cast<float4*>(&prow[(size_t)(r0 + 64) * kS + k0 + c0]) = n1v;
        __syncthreads();

#pragma unroll
        for (int kk = 0; kk < 16; ++kk) {
            float4 a0 = *reinterpret_cast<const float4*>(&As[kk][ty * 8]);
            float4 a1 = *reinterpret_cast<const float4*>(&As[kk][ty * 8 + 4]);
            ulonglong2 ub = *reinterpret_cast<const ulonglong2*>(&Bs[kk][tx * 4]);
            unsigned long long bp[2] = {ub.x, ub.y};
            unsigned long long ad[8];
            ad[0] = pack_dup(a0.x); ad[1] = pack_dup(a0.y);
            ad[2] = pack_dup(a0.z); ad[3] = pack_dup(a0.w);
            ad[4] = pack_dup(a1.x); ad[5] = pack_dup(a1.y);
            ad[6] = pack_dup(a1.z); ad[7] = pack_dup(a1.w);
#pragma unroll
            for (int i = 0; i < 8; ++i) {
                fma_x2(acc2[i][0], ad[i], bp[0]);
                fma_x2(acc2[i][1], ad[i], bp[1]);
            }
        }
    }

    float* __restrict__ orow = out + (size_t)bh * kS * kDK;
#pragma unroll
    for (int i = 0; i < 8; ++i) {
        float4 o;
        unpack_x2(acc2[i][0], o.x, o.y);
        unpack_x2(acc2[i][1], o.z, o.w);
        *reinterpret_cast<float4*>(&orow[(m0 + ty * 8 + i) * kDK + tx * 4]) = o;
    }
}

// ===========================================================================
extern "C" void kernel_launch(void* const* d_in, const int* in_sizes, int n_in,
                              void* d_out, int out_size)
{
    (void)in_sizes; (void)n_in; (void)out_size;
    const float* query = (const float*)d_in[0];
    const float* key   = (const float*)d_in[1];
    const float* value = (const float*)d_in[2];
    const float* r     = (const float*)d_in[3];
    const int*   mask  = (const int*)  d_in[4];
    const float* Wq = (const float*)d_in[5];  const float* bq = (const float*)d_in[6];
    const float* Wk = (const float*)d_in[7];  const float* bk = (const float*)d_in[8];
    const float* Wv = (const float*)d_in[9];  const float* bv = (const float*)d_in[10];
    const float* Wr = (const float*)d_in[11]; const float* br = (const float*)d_in[12];

    float* out = (float*)d_out;                          // (B,H,S,DK)
    float* p   = out + (size_t)kBH * kS * kDK;           // (B,H,S,S)

    cudaFuncSetAttribute(proj_mma_kernel,
                         cudaFuncAttributeMaxDynamicSharedMemorySize, kPSmem);

    dim3 pgrid(kD / 128, kBS / 128);                     // (8, 32)
    proj_mma_kernel<<<pgrid, 256, kPSmem>>>(query, Wq, bq, nullptr, nullptr, nullptr, 0, 32);
    proj_mma_kernel<<<pgrid, 256, kPSmem>>>(key,   Wk, bk, r, Wr, br, 1, 64);  // kr
    proj_mma_kernel<<<pgrid, 256, kPSmem>>>(value, Wv, bv, nullptr, nullptr, nullptr, 2, 32);

    dim3 sgrid(kS / 128, kBH);                           // (16, 32)
    scores_sum_kernel<<<sgrid, 256>>>(mask, p);

    dim3 ogrid(kS / 128, kBH);                           // (16, 32)
    out_kernel<<<ogrid, 256>>>(p, out);
}

// round 11
// speedup vs baseline: 1.2503x; 1.1485x over previous
#include <cuda_runtime.h>
#include <cstdint>

// ===========================================================================
// Problem constants
// ===========================================================================
namespace {
constexpr int kB  = 2;
constexpr int kS  = 2048;
constexpr int kD  = 1024;
constexpr int kH  = 16;
constexpr int kDK = 64;
constexpr int kBH = kB * kH;        // 32
constexpr int kBS = kB * kS;        // 4096
constexpr int kNRows = kBH * kS;    // 65536

// proj smem: Ah/Al/Bh/Bl [128 rows][36 floats] (stride 36: 144B = 9 granules,
// conflict-free for ldmatrix; k = 0..31)
constexpr int kPRS   = 36;
constexpr int kPTile = 128 * kPRS;                 // floats per tile
constexpr int kPSmem = 4 * kPTile * 4;             // 73728 bytes

// scores smem: Qh/Ql [128][68] + Kh/Kl [64][68] (stride 68: 272B = 17 granules)
constexpr int kQRS   = 68;
constexpr int kQTile = 128 * kQRS;
constexpr int kKTile = 64 * kQRS;
constexpr int kSSmem = (2 * kQTile + 2 * kKTile) * 4;   // 104448 bytes
}

// Scratch (allocation-free rule: __device__ globals)
__device__ float g_q [kBH * kS * kDK];   // 16 MB
__device__ float g_kr[kBH * kS * kDK];   // 16 MB (k_proj + r_proj)
__device__ float g_v [kBH * kS * kDK];   // 16 MB
__device__ float g_rinv[kNRows];

// ===========================================================================
// helpers (arch-neutral PTX, valid on sm_100 target)
// ===========================================================================
__device__ __forceinline__ void split_tf32(float x, uint32_t& hi, uint32_t& lo) {
    uint32_t h;
    asm("cvt.rna.tf32.f32 %0, %1;" : "=r"(h) : "f"(x));
    float lf = x - __uint_as_float(h);
    uint32_t l;
    asm("cvt.rna.tf32.f32 %0, %1;" : "=r"(l) : "f"(lf));
    hi = h; lo = l;
}

// D += A(tf32) * B(tf32); m16n8k8, A row-major, B col-major.
__device__ __forceinline__ void mma_m16n8k8_tf32(float* d, const uint32_t* a,
                                                 const uint32_t* b) {
    asm volatile(
        "mma.sync.aligned.m16n8k8.row.col.f32.tf32.tf32.f32 "
        "{%0,%1,%2,%3}, {%4,%5,%6,%7}, {%8,%9}, {%0,%1,%2,%3};"
        : "+f"(d[0]), "+f"(d[1]), "+f"(d[2]), "+f"(d[3])
        : "r"(a[0]), "r"(a[1]), "r"(a[2]), "r"(a[3]), "r"(b[0]), "r"(b[1]));
}

__device__ __forceinline__ void ldsm_x4(uint32_t* r, uint32_t saddr) {
    asm volatile("ldmatrix.sync.aligned.m8n8.x4.shared.b16 {%0,%1,%2,%3}, [%4];"
        : "=r"(r[0]), "=r"(r[1]), "=r"(r[2]), "=r"(r[3]) : "r"(saddr));
}
__device__ __forceinline__ void ldsm_x2(uint32_t* r, uint32_t saddr) {
    asm volatile("ldmatrix.sync.aligned.m8n8.x2.shared.b16 {%0,%1}, [%2];"
        : "=r"(r[0]), "=r"(r[1]) : "r"(saddr));
}
__device__ __forceinline__ uint32_t smem_u32(const void* p) {
    return (uint32_t)__cvta_generic_to_shared(p);
}

// ===========================================================================
// Projection GEMM via mma.sync tf32x3, hi/lo pre-split in smem, ldmatrix
// fragment loads ([row][k] layout, stride 36 floats, conflict-free).
//   D[m,e] = sum_d X1[m,d]*W1[e,d]  (+ X2[m,d]*W2[e,d] if ns==64) + bias
// 128x128 CTA tile, BK=32, 8 warps as 2(m) x 4(n); warp tile 64x32.
// ===========================================================================
__global__ __launch_bounds__(256) void proj_mma_kernel(
    const float* __restrict__ X1, const float* __restrict__ W1, const float* __restrict__ b1,
    const float* __restrict__ X2, const float* __restrict__ W2, const float* __restrict__ b2,
    int dst_sel, int ns)
{
    extern __shared__ uint32_t smem_u[];
    uint32_t* Ah = smem_u;
    uint32_t* Al = smem_u + kPTile;
    uint32_t* Bh = smem_u + 2 * kPTile;
    uint32_t* Bl = smem_u + 3 * kPTile;
    const uint32_t ah_b = smem_u32(Ah), al_b = smem_u32(Al);
    const uint32_t bh_b = smem_u32(Bh), bl_b = smem_u32(Bl);

    const int tid   = threadIdx.x;
    const int wid   = tid >> 5;
    const int lane  = tid & 31;
    const int gid   = lane >> 2;          // 0..7
    const int tid4  = lane & 3;           // 0..3
    const int wm    = (wid >> 2) * 64;    // warp m-offset: 0 / 64
    const int wn    = (wid & 3) * 32;     // warp n-offset: 0/32/64/96
    const int m0    = blockIdx.y * 128;
    const int n0    = blockIdx.x * 128;

    // ldmatrix per-lane row/col offsets
    const int a_row = lane & 15;               // x4: 16 rows
    const int a_ko  = ((lane >> 4) & 1) << 2;  // 0 / 4
    const int b_row = lane & 7;                // x2: 8 rows (lanes 0-15 used)
    const int b_ko  = ((lane >> 3) & 1) << 2;

    float acc[4][4][4];
#pragma unroll
    for (int mt = 0; mt < 4; ++mt)
#pragma unroll
        for (int nt = 0; nt < 4; ++nt)
#pragma unroll
            for (int f = 0; f < 4; ++f) acc[mt][nt][f] = 0.f;

    for (int s = 0; s < ns; ++s) {
        const float* __restrict__ X = (s < 32) ? X1 : X2;
        const float* __restrict__ W = (s < 32) ? W1 : W2;
        const int k0 = (s & 31) * 32;

        float4 xa[4], wb[4];
#pragma unroll
        for (int i = 0; i < 4; ++i) {
            const int idx = tid + 256 * i;       // 0..1023
            const int row = idx >> 3;            // 0..127
            const int c4  = (idx & 7) * 4;       // 0..28
            xa[i] = *reinterpret_cast<const float4*>(&X[(size_t)(m0 + row) * kD + k0 + c4]);
            wb[i] = *reinterpret_cast<const float4*>(&W[(size_t)(n0 + row) * kD + k0 + c4]);
        }
        __syncthreads();
#pragma unroll
        for (int i = 0; i < 4; ++i) {
            const int idx = tid + 256 * i;
            const int row = idx >> 3;
            const int c4  = (idx & 7) * 4;
            const float* xv = reinterpret_cast<const float*>(&xa[i]);
            const float* wv = reinterpret_cast<const float*>(&wb[i]);
#pragma unroll
            for (int j = 0; j < 4; ++j) {
                uint32_t h, l;
                split_tf32(xv[j], h, l);
                Ah[row * kPRS + c4 + j] = h;
                Al[row * kPRS + c4 + j] = l;
                split_tf32(wv[j], h, l);
                Bh[row * kPRS + c4 + j] = h;
                Bl[row * kPRS + c4 + j] = l;
            }
        }
        __syncthreads();

#pragma unroll
        for (int kk = 0; kk < 4; ++kk) {
            const int kb = kk * 8;

            uint32_t bhf[4][2], blf[4][2];
#pragma unroll
            for (int nt = 0; nt < 4; ++nt) {
                const uint32_t off =
                    (uint32_t)(((wn + nt * 8 + b_row) * kPRS + kb + b_ko) * 4);
                ldsm_x2(bhf[nt], bh_b + off);
                ldsm_x2(blf[nt], bl_b + off);
            }

#pragma unroll
            for (int mt = 0; mt < 4; ++mt) {
                const uint32_t off =
                    (uint32_t)(((wm + mt * 16 + a_row) * kPRS + kb + a_ko) * 4);
                uint32_t ah[4], al[4];
                ldsm_x4(ah, ah_b + off);
                ldsm_x4(al, al_b + off);
#pragma unroll
                for (int nt = 0; nt < 4; ++nt) {
                    mma_m16n8k8_tf32(acc[mt][nt], ah, bhf[nt]);
                    mma_m16n8k8_tf32(acc[mt][nt], ah, blf[nt]);
                    mma_m16n8k8_tf32(acc[mt][nt], al, bhf[nt]);
                }
            }
        }
    }

    float* __restrict__ dst = (dst_sel == 0) ? g_q : (dst_sel == 1) ? g_kr : g_v;
#pragma unroll
    for (int nt = 0; nt < 4; ++nt) {
        const int e  = n0 + wn + nt * 8 + 2 * tid4;
        const int h  = e >> 6;
        const int dk = e & 63;
        float2 bb;
        bb.x = b1[e];     bb.y = b1[e + 1];
        if (X2) { bb.x += b2[e]; bb.y += b2[e + 1]; }
#pragma unroll
        for (int mt = 0; mt < 4; ++mt) {
#pragma unroll
            for (int half = 0; half < 2; ++half) {
                const int gm   = m0 + wm + mt * 16 + gid + half * 8;
                const int bidx = gm >> 11;
                const int srow = gm & (kS - 1);
                float2 o;
                o.x = acc[mt][nt][half * 2 + 0] + bb.x;
                o.y = acc[mt][nt][half * 2 + 1] + bb.y;
                *reinterpret_cast<float2*>(
                    &dst[(((size_t)bidx * kH + h) * kS + srow) * kDK + dk]) = o;
            }
        }
    }
}

// ===========================================================================
// Fused scores + softmax numerator + row sums via mma.sync tf32x3 + ldmatrix.
//   e = mask ? exp(q@kr^T * scale) : 0  -> p (numerators);  g_rinv = 1/rowsum
// CTA: 128 q-rows; KR streamed in 64-row chunks. Q/KR hi/lo pre-split in
// smem [row][k] stride 68. 8 warps as 2(m) x 4(n); warp tile 64m x 16n.
// grid (S/128, BH), 256 threads, dynamic smem kSSmem, 2 CTAs/SM.
// ===========================================================================
__global__ __launch_bounds__(256, 2) void scores_mma_kernel(const int* __restrict__ mask,
                                                            float* __restrict__ p)
{
    extern __shared__ uint32_t smem_u[];
    uint32_t* Qh = smem_u;
    uint32_t* Ql = smem_u + kQTile;
    uint32_t* Kh = smem_u + 2 * kQTile;
    uint32_t* Kl = smem_u + 2 * kQTile + kKTile;
    const uint32_t qh_b = smem_u32(Qh), ql_b = smem_u32(Ql);
    const uint32_t kh_b = smem_u32(Kh), kl_b = smem_u32(Kl);
    __shared__ float rs[128];

    const int tid   = threadIdx.x;
    const int wid   = tid >> 5;
    const int lane  = tid & 31;
    const int gid   = lane >> 2;
    const int tid4  = lane & 3;
    const int wm    = (wid >> 2) * 64;     // 0 / 64
    const int wn    = (wid & 3) * 16;      // 0/16/32/48
    const int bh    = blockIdx.y;
    const int m0    = blockIdx.x * 128;
    const int b_    = bh >> 4;
    const float scale = 0.125f;

    const int a_row = lane & 15;
    const int a_ko  = ((lane >> 4) & 1) << 2;
    const int b_row = lane & 7;
    const int b_ko  = ((lane >> 3) & 1) << 2;

    const float* __restrict__ Q  = g_q  + (size_t)bh * kS * kDK;
    const float* __restrict__ KR = g_kr + (size_t)bh * kS * kDK;

    if (tid < 128) rs[tid] = 0.f;

    // ---- load + split Q strip (128 x 64) into Qh/Ql [m][k] ----
    for (int i = tid; i < 128 * 16; i += 256) {
        const int row = i >> 4;
        const int kq  = (i & 15) * 4;
        float4 v = *reinterpret_cast<const float4*>(&Q[(size_t)(m0 + row) * kDK + kq]);
        const float* vv = reinterpret_cast<const float*>(&v);
#pragma unroll
        for (int j = 0; j < 4; ++j) {
            uint32_t h, l;
            split_tf32(vv[j], h, l);
            Qh[row * kQRS + kq + j] = h;
            Ql[row * kQRS + kq + j] = l;
        }
    }

    float rsum[4][2];
#pragma unroll
    for (int mt = 0; mt < 4; ++mt) { rsum[mt][0] = 0.f; rsum[mt][1] = 0.f; }

    for (int nb = 0; nb < kS; nb += 64) {
        __syncthreads();   // previous chunk's ldmatrix reads done
        // ---- load + split KR chunk (64 x 64) into Kh/Kl [n][k] ----
        for (int i = tid; i < 64 * 16; i += 256) {
            const int n  = i >> 4;
            const int kq = (i & 15) * 4;
            float4 v = *reinterpret_cast<const float4*>(&KR[(size_t)(nb + n) * kDK + kq]);
            const float* vv = reinterpret_cast<const float*>(&v);
#pragma unroll
            for (int j = 0; j < 4; ++j) {
                uint32_t h, l;
                split_tf32(vv[j], h, l);
                Kh[n * kQRS + kq + j] = h;
                Kl[n * kQRS + kq + j] = l;
            }
        }
        __syncthreads();

        float acc[4][2][4];
#pragma unroll
        for (int mt = 0; mt < 4; ++mt)
#pragma unroll
            for (int nt = 0; nt < 2; ++nt)
#pragma unroll
                for (int f = 0; f < 4; ++f) acc[mt][nt][f] = 0.f;

        // ---- 8 k8-steps over DK=64, ldmatrix fragment loads ----
#pragma unroll
        for (int kk = 0; kk < 8; ++kk) {
            const int kb = kk * 8;

            uint32_t bhf[2][2], blf[2][2];
#pragma unroll
            for (int nt = 0; nt < 2; ++nt) {
                const uint32_t off =
                    (uint32_t)(((wn + nt * 8 + b_row) * kQRS + kb + b_ko) * 4);
                ldsm_x2(bhf[nt], kh_b + off);
                ldsm_x2(blf[nt], kl_b + off);
            }

#pragma unroll
            for (int mt = 0; mt < 4; ++mt) {
                const uint32_t off =
                    (uint32_t)(((wm + mt * 16 + a_row) * kQRS + kb + a_ko) * 4);
                uint32_t ah[4], al[4];
                ldsm_x4(ah, qh_b + off);
                ldsm_x4(al, ql_b + off);
#pragma unroll
                for (int nt = 0; nt < 2; ++nt) {
                    mma_m16n8k8_tf32(acc[mt][nt], ah, bhf[nt]);
                    mma_m16n8k8_tf32(acc[mt][nt], ah, blf[nt]);
                    mma_m16n8k8_tf32(acc[mt][nt], al, bhf[nt]);
                }
            }
        }

        // ---- epilogue: mask -> exp -> store numerators -> row partials ----
#pragma unroll
        for (int mt = 0; mt < 4; ++mt) {
#pragma unroll
            for (int nt = 0; nt < 2; ++nt) {
                const int sk = nb + wn + nt * 8 + 2 * tid4;
#pragma unroll
                for (int half = 0; half < 2; ++half) {
                    const int sq = m0 + wm + mt * 16 + gid + half * 8;
                    int2 mm = *reinterpret_cast<const int2*>(
                        &mask[((size_t)b_ * kS + sq) * kS + sk]);
                    const float f0 = acc[mt][nt][half * 2 + 0] * scale;
                    const float f1 = acc[mt][nt][half * 2 + 1] * scale;
                    float2 e;
                    e.x = mm.x ? __expf(f0) : 0.f;
                    e.y = mm.y ? __expf(f1) : 0.f;
                    *reinterpret_cast<float2*>(
                        &p[((size_t)bh * kS + sq) * kS + sk]) = e;
                    rsum[mt][half] += e.x + e.y;
                }
            }
        }
    }

    // ---- final row-sum reduction ----
    __syncthreads();
#pragma unroll
    for (int mt = 0; mt < 4; ++mt) {
#pragma unroll
        for (int half = 0; half < 2; ++half) {
            float s = rsum[mt][half];
            s += __shfl_xor_sync(0xffffffffu, s, 1);
            s += __shfl_xor_sync(0xffffffffu, s, 2);
            if (tid4 == 0)
                atomicAdd(&rs[wm + mt * 16 + gid + half * 8], s);
        }
    }
    __syncthreads();
    if (tid < 128) g_rinv[bh * kS + m0 + tid] = 1.0f / rs[tid];
}

// ===========================================================================
// out = p @ v with on-the-fly normalization; writes final p back.
// R8 version verbatim (measured ~453us).
// ===========================================================================
__global__ __launch_bounds__(256, 2) void out_kernel(float* __restrict__ p,
                                                     float* __restrict__ out)
{
    __shared__ float As[16][128];
    __shared__ float Bs[16][64];
    __shared__ float s_inv[128];

    const int bh  = blockIdx.y;
    const int m0  = blockIdx.x * 128;
    const int tid = threadIdx.x;
    const int tx  = tid & 15;
    const int ty  = tid >> 4;

    if (tid < 128) {
        s_inv[tid] = g_rinv[bh * kS + m0 + tid];
    }
    __syncthreads();

    float acc[8][4];
#pragma unroll
    for (int i = 0; i < 8; ++i)
#pragma unroll
        for (int j = 0; j < 4; ++j) acc[i][j] = 0.f;

    float* __restrict__ prow = p + (size_t)bh * kS * kS + (size_t)m0 * kS;
    const float* __restrict__ V = g_v + (size_t)bh * kS * kDK;

    const int r0 = tid >> 2;
    const int c0 = (tid & 3) * 4;
    const int vk = tid >> 4;
    const int vn = (tid & 15) * 4;

    const float iv0 = s_inv[r0];
    const float iv1 = s_inv[r0 + 64];

    for (int k0 = 0; k0 < kS; k0 += 16) {
        float4 x0 = *reinterpret_cast<const float4*>(&prow[(size_t)r0 * kS + k0 + c0]);
        float4 x1 = *reinterpret_cast<const float4*>(&prow[(size_t)(r0 + 64) * kS + k0 + c0]);
        float4 n0v, n1v;
        n0v.x = x0.x * iv0;  n0v.y = x0.y * iv0;
        n0v.z = x0.z * iv0;  n0v.w = x0.w * iv0;
        n1v.x = x1.x * iv1;  n1v.y = x1.y * iv1;
        n1v.z = x1.z * iv1;  n1v.w = x1.w * iv1;

        float4 vb = *reinterpret_cast<const float4*>(&V[(k0 + vk) * kDK + vn]);

        __syncthreads();
        As[c0 + 0][r0]      = n0v.x; As[c0 + 1][r0]      = n0v.y;
        As[c0 + 2][r0]      = n0v.z; As[c0 + 3][r0]      = n0v.w;
        As[c0 + 0][r0 + 64] = n1v.x; As[c0 + 1][r0 + 64] = n1v.y;
        As[c0 + 2][r0 + 64] = n1v.z; As[c0 + 3][r0 + 64] = n1v.w;
        *reinterpret_cast<float4*>(&Bs[vk][vn]) = vb;

        *reinterpret_cast<float4*>(&prow[(size_t)r0 * kS + k0 + c0])        = n0v;
        *reinterpret_cast<float4*>(&prow[(size_t)(r0 + 64) * kS + k0 + c0]) = n1v;
        __syncthreads();

#pragma unroll
        for (int kk = 0; kk < 16; ++kk) {
            float4 a0 = *reinterpret_cast<const float4*>(&As[kk][ty * 8]);
            float4 a1 = *reinterpret_cast<const float4*>(&As[kk][ty * 8 + 4]);
            float4 bb = *reinterpret_cast<const float4*>(&Bs[kk][tx * 4]);
            float a[8]  = {a0.x, a0.y, a0.z, a0.w, a1.x, a1.y, a1.z, a1.w};
            float bj[4] = {bb.x, bb.y, bb.z, bb.w};
#pragma unroll
            for (int i = 0; i < 8; ++i)
#pragma unroll
                for (int j = 0; j < 4; ++j) acc[i][j] += a[i] * bj[j];
        }
    }

    float* __restrict__ orow = out + (size_t)bh * kS * kDK;
#pragma unroll
    for (int i = 0; i < 8; ++i) {
        float4 o = make_float4(acc[i][0], acc[i][1], acc[i][2], acc[i][3]);
        *reinterpret_cast<float4*>(&orow[(m0 + ty * 8 + i) * kDK + tx * 4]) = o;
    }
}

// ===========================================================================
extern "C" void kernel_launch(void* const* d_in, const int* in_sizes, int n_in,
                              void* d_out, int out_size)
{
    (void)in_sizes; (void)n_in; (void)out_size;
    const float* query = (const float*)d_in[0];
    const float* key   = (const float*)d_in[1];
    const float* value = (const float*)d_in[2];
    const float* r     = (const float*)d_in[3];
    const int*   mask  = (const int*)  d_in[4];
    const float* Wq = (const float*)d_in[5];  const float* bq = (const float*)d_in[6];
    const float* Wk = (const float*)d_in[7];  const float* bk = (const float*)d_in[8];
    const float* Wv = (const float*)d_in[9];  const float* bv = (const float*)d_in[10];
    const float* Wr = (const float*)d_in[11]; const float* br = (const float*)d_in[12];

    float* out = (float*)d_out;                          // (B,H,S,DK)
    float* p   = out + (size_t)kBH * kS * kDK;           // (B,H,S,S)

    cudaFuncSetAttribute(proj_mma_kernel,
                         cudaFuncAttributeMaxDynamicSharedMemorySize, kPSmem);
    cudaFuncSetAttribute(scores_mma_kernel,
                         cudaFuncAttributeMaxDynamicSharedMemorySize, kSSmem);

    dim3 pgrid(kD / 128, kBS / 128);                     // (8, 32)
    proj_mma_kernel<<<pgrid, 256, kPSmem>>>(query, Wq, bq, nullptr, nullptr, nullptr, 0, 32);
    proj_mma_kernel<<<pgrid, 256, kPSmem>>>(key,   Wk, bk, r, Wr, br, 1, 64);  // kr
    proj_mma_kernel<<<pgrid, 256, kPSmem>>>(value, Wv, bv, nullptr, nullptr, nullptr, 2, 32);

    dim3 sgrid(kS / 128, kBH);                           // (16, 32)
    scores_mma_kernel<<<sgrid, 256, kSSmem>>>(mask, p);

    dim3 ogrid(kS / 128, kBH);                           // (16, 32)
    out_kernel<<<ogrid, 256>>>(p, out);
}